// round 16
// baseline (speedup 1.0000x reference)
#include <cuda_runtime.h>
#include <cuda_fp16.h>
#include <cstdint>

// ---------------------------------------------------------------------------
// FixedTopKLoRALinear: out = x@W^T + bias + softtopk(x@A^T)@B^T
// x[8192,4096], A[64,4096], B[4096,64], W[4096,4096], bias[4096]
//
// fp16 m16n8k16 mma.sync, fp32 accum. Main GEMM is HMMA-rate-pinned
// (R11==R12 invariance); this round hides all preprocessing under it via a
// single fused kernel with device-flag producer/consumer sync:
//   bid   0..127 : z-role  (A-cvt prologue on bid<64; x cvt + z=x@A^T + topk)
//   bid 128..255 : cvt-role (W -> fp16 per-ktile flags; B -> fp16)
//   bid 256..2303: main-GEMM role (gates issue_copy on flags until done)
// __launch_bounds__(128,2) guarantees occupancy>=2 so wave-1 (>=296 CTAs)
// contains all 256 producers -> deadlock-free. Flags reset each call by a
// tiny reset kernel (graph-replay determinism).
// ---------------------------------------------------------------------------

#define D_IN_C   4096
#define D_IN_P   2048          // fp16 pairs per x/W/A row
#define N_FIX    4096
#define R_C      64
#define R_P      32            // fp16 pairs per zs/B row
#define KSEL_C   16
#define TEMP_C   0.1f
#define MAX_M    8192
#define PITCH    36            // uint32 words per smem row

#define NZ       128           // z-role CTAs
#define NCVT     128           // cvt-role CTAs
#define NPROD    (NZ + NCVT)   // 256
#define NMAIN    2048
#define KT_MAIN  64            // 4096/64

// Flags (single array; reset each call)
#define F_A      0                     // [64]   A ktile converted
#define F_X      64                    // [128*64] xh (64-row block, ktile)
#define F_ZS     (F_X + 128*64)        // [128]  zsh 64-row block done
#define F_W      (F_ZS + 128)          // [32*64] wh (128-row block, ktile)
#define F_B      (F_W + 32*64)         // [32]   bh 128-row block done
#define F_DONE   (F_B + 32)            // [1]    producer completion count
#define F_TOTAL  (F_DONE + 1)

__device__ int g_flags[F_TOTAL];

// Scratch (allocation-free: device globals)
__device__ uint32_t g_xh [MAX_M * D_IN_P];
__device__ uint32_t g_wh [N_FIX * D_IN_P];
__device__ uint32_t g_ah [R_C   * D_IN_P];
__device__ uint32_t g_bh [N_FIX * R_P];
__device__ uint32_t g_zsh[MAX_M * R_P];

// ---------------------------------------------------------------------------
__device__ __forceinline__ uint32_t pack2(float a, float b) {
    __half2 h = __floats2half2_rn(a, b);
    return *(uint32_t*)&h;
}

__device__ __forceinline__ void mma_f16(float* d, const uint32_t* a, const uint32_t* b) {
    asm volatile(
        "mma.sync.aligned.m16n8k16.row.col.f32.f16.f16.f32 "
        "{%0,%1,%2,%3},{%4,%5,%6,%7},{%8,%9},{%0,%1,%2,%3};"
        : "+f"(d[0]), "+f"(d[1]), "+f"(d[2]), "+f"(d[3])
        : "r"(a[0]), "r"(a[1]), "r"(a[2]), "r"(a[3]), "r"(b[0]), "r"(b[1]));
}

__device__ __forceinline__ void cp_async16(uint32_t* dst_smem, const uint32_t* src_gmem) {
    uint32_t s = (uint32_t)__cvta_generic_to_shared(dst_smem);
    asm volatile("cp.async.cg.shared.global [%0], [%1], 16;\n" :: "r"(s), "l"(src_gmem));
}
#define CPA_COMMIT() asm volatile("cp.async.commit_group;" ::: "memory")
#define CPA_WAIT(n)  asm volatile("cp.async.wait_group %0;" :: "n"(n) : "memory")

__device__ __forceinline__ void spin_flag(const int* f) {
    while (*(volatile const int*)f == 0)
        asm volatile("nanosleep.u32 128;");
}
__device__ __forceinline__ void set_flag(int* f) {   // caller fenced+synced
    *(volatile int*)f = 1;
}

// ===========================================================================
// Kernel 1: reset flags.
// ===========================================================================
__global__ void reset_flags_kernel()
{
    int i = blockIdx.x * blockDim.x + threadIdx.x;
    const int stride = gridDim.x * blockDim.x;
    for (; i < F_TOTAL; i += stride) g_flags[i] = 0;
}

// ===========================================================================
// Kernel 2: fused everything.
// ===========================================================================
__global__ void __launch_bounds__(128, 2)
fused_kernel(const float4* __restrict__ x,
             const float4* __restrict__ A,
             const float4* __restrict__ B,
             const float4* __restrict__ W,
             const float* __restrict__ bias,
             float* __restrict__ out)
{
    extern __shared__ uint32_t smem[];
    const int bid  = blockIdx.x;
    const int tid  = threadIdx.x;
    const int lane = tid & 31;
    const int wid  = tid >> 5;

    // =======================================================================
    // z-role
    // =======================================================================
    if (bid < NZ) {
        // ---- A-cvt prologue (bids 0..63): A cols [bid*64,(bid+1)*64) ----
        if (bid < KT_MAIN) {
#pragma unroll
            for (int i = 0; i < 8; i++) {
                int idx = tid + i * 128;          // 0..1023 (64 rows x 16 f4)
                int row = idx >> 4, c4 = idx & 15;
                float4 v = A[(size_t)row * 1024 + (size_t)bid * 16 + c4];
                uint2 o;
                o.x = pack2(v.x, v.y);
                o.y = pack2(v.z, v.w);
                ((uint2*)g_ah)[(size_t)row * 1024 + (size_t)bid * 16 + c4] = o;
            }
            __threadfence();
            __syncthreads();
            if (tid == 0) set_flag(&g_flags[F_A + bid]);
        }

        uint32_t* As = smem;                  // [2][64][PITCH]
        uint32_t* Bs = smem + 2 * 64 * PITCH; // [2][64][PITCH]
        float*    zbuf = (float*)smem;        // [64][65] aliased after MMAs

        const int wm   = wid >> 1;
        const int wn   = wid & 1;
        const int bm   = bid * 64;
        const int col4 = tid & 15;
        const int row0 = tid >> 4;

        float acc[2][4][4];
#pragma unroll
        for (int mt = 0; mt < 2; mt++)
#pragma unroll
            for (int nt = 0; nt < 4; nt++)
#pragma unroll
                for (int e = 0; e < 4; e++) acc[mt][nt][e] = 0.0f;

        auto ldg_x = [&](int kb, float4* r) {
#pragma unroll
            for (int i = 0; i < 8; i++)
                r[i] = x[(size_t)(bm + row0 + i * 8) * 1024 + kb * 16 + col4];
        };
        auto gate_a = [&](int kb) {
            if (tid == 0) { spin_flag(&g_flags[F_A + kb]); __threadfence(); }
            __syncthreads();
        };
        auto cpa_b = [&](int kb, int s) {
            uint32_t* bs = Bs + s * 64 * PITCH;
#pragma unroll
            for (int i = 0; i < 4; i++) {
                int linear = tid + i * 128;
                int row = linear >> 3;
                int cv  = (linear & 7) << 2;
                cp_async16(&bs[row * PITCH + cv],
                           g_ah + (size_t)row * D_IN_P + kb * 32 + cv);
            }
            CPA_COMMIT();
        };
        auto sts_stg = [&](int kb, int s, const float4* r) {
            uint32_t* as = As + s * 64 * PITCH;
            uint2* xo = (uint2*)g_xh;
#pragma unroll
            for (int i = 0; i < 8; i++) {
                uint2 v;
                v.x = pack2(r[i].x, r[i].y);
                v.y = pack2(r[i].z, r[i].w);
                int row = row0 + i * 8;
                *(uint2*)&as[row * PITCH + col4 * 2] = v;
                xo[(size_t)(bm + row) * 1024 + kb * 16 + col4] = v;
            }
        };
        auto mma_tile = [&](int s) {
            const uint32_t* as = As + s * 64 * PITCH + (wm * 32) * PITCH;
            const uint32_t* bs = Bs + s * 64 * PITCH + (wn * 32) * PITCH;
#pragma unroll
            for (int kk = 0; kk < 4; kk++) {
                uint32_t afrag[2][4];
#pragma unroll
                for (int mt = 0; mt < 2; mt++) {
                    int r = mt * 16 + (lane >> 2);
                    int c = kk * 8 + (lane & 3);
                    afrag[mt][0] = as[r * PITCH + c];
                    afrag[mt][1] = as[(r + 8) * PITCH + c];
                    afrag[mt][2] = as[r * PITCH + c + 4];
                    afrag[mt][3] = as[(r + 8) * PITCH + c + 4];
                }
                uint32_t bfrag[4][2];
#pragma unroll
                for (int nt = 0; nt < 4; nt++) {
                    int n = nt * 8 + (lane >> 2);
                    int c = kk * 8 + (lane & 3);
                    bfrag[nt][0] = bs[n * PITCH + c];
                    bfrag[nt][1] = bs[n * PITCH + c + 4];
                }
#pragma unroll
                for (int mt = 0; mt < 2; mt++)
#pragma unroll
                    for (int nt = 0; nt < 4; nt++)
                        mma_f16(acc[mt][nt], afrag[mt], bfrag[nt]);
            }
        };

        float4 rA[8], rB[8];
        ldg_x(0, rA);
        gate_a(0);
        cpa_b(0, 0);

        for (int kb2 = 0; kb2 < KT_MAIN; kb2 += 2) {
            // even tile -> stage 0
            if (kb2 + 1 < KT_MAIN) {
                ldg_x(kb2 + 1, rB);
                gate_a(kb2 + 1);
                cpa_b(kb2 + 1, 1);
            }
            sts_stg(kb2, 0, rA);
            __threadfence();
            if (kb2 + 1 < KT_MAIN) { CPA_WAIT(1); } else { CPA_WAIT(0); }
            __syncthreads();
            if (tid == 0) set_flag(&g_flags[F_X + bid * 64 + kb2]);
            mma_tile(0);
            __syncthreads();
            // odd tile -> stage 1
            if (kb2 + 1 < KT_MAIN) {
                if (kb2 + 2 < KT_MAIN) {
                    ldg_x(kb2 + 2, rA);
                    gate_a(kb2 + 2);
                    cpa_b(kb2 + 2, 0);
                }
                sts_stg(kb2 + 1, 1, rB);
                __threadfence();
                if (kb2 + 2 < KT_MAIN) { CPA_WAIT(1); } else { CPA_WAIT(0); }
                __syncthreads();
                if (tid == 0) set_flag(&g_flags[F_X + bid * 64 + kb2 + 1]);
                mma_tile(1);
                __syncthreads();
            }
        }

        // ---- z -> smem (pitch 65 floats) ----
#pragma unroll
        for (int mt = 0; mt < 2; mt++)
#pragma unroll
            for (int nt = 0; nt < 4; nt++) {
                int r0 = wm * 32 + mt * 16 + (lane >> 2);
                int c0 = wn * 32 + nt * 8 + (lane & 3) * 2;
                zbuf[r0 * 65 + c0]           = acc[mt][nt][0];
                zbuf[r0 * 65 + c0 + 1]       = acc[mt][nt][1];
                zbuf[(r0 + 8) * 65 + c0]     = acc[mt][nt][2];
                zbuf[(r0 + 8) * 65 + c0 + 1] = acc[mt][nt][3];
            }
        __syncthreads();

        // ---- soft top-k per row; warp w handles rows w*16..w*16+15 ----
        const float inv_t = 1.0f / TEMP_C;
        for (int rr = 0; rr < 16; rr++) {
            const int row = wid * 16 + rr;
            float z0 = zbuf[row * 65 + lane];
            float z1 = zbuf[row * 65 + lane + 32];
            float v0 = fabsf(z0), v1 = fabsf(z1);
            bool a0 = true, a1 = true;
            float thr = 0.0f;
#pragma unroll 1
            for (int it = 0; it < KSEL_C; it++) {
                float m = fmaxf(a0 ? v0 : -1.0f, a1 ? v1 : -1.0f);
#pragma unroll
                for (int off = 16; off; off >>= 1)
                    m = fmaxf(m, __shfl_xor_sync(0xffffffffu, m, off));
                thr = m;
                unsigned b = __ballot_sync(0xffffffffu, a0 && v0 == m);
                if (b) {
                    if (lane == (__ffs(b) - 1)) a0 = false;
                } else {
                    unsigned b2 = __ballot_sync(0xffffffffu, a1 && v1 == m);
                    if (lane == (__ffs(b2) - 1)) a1 = false;
                }
            }
            float zs0 = z0 * (1.0f / (1.0f + expf(-(v0 - thr) * inv_t)));
            float zs1 = z1 * (1.0f / (1.0f + expf(-(v1 - thr) * inv_t)));
            zbuf[row * 65 + lane]      = zs0;
            zbuf[row * 65 + lane + 32] = zs1;
            __syncwarp();
            g_zsh[(size_t)(bm + row) * R_P + lane] =
                pack2(zbuf[row * 65 + 2 * lane], zbuf[row * 65 + 2 * lane + 1]);
            __syncwarp();
        }
        __threadfence();
        __syncthreads();
        if (tid == 0) {
            set_flag(&g_flags[F_ZS + bid]);
            atomicAdd(&g_flags[F_DONE], 1);
        }
        return;
    }

    // =======================================================================
    // cvt-role: W (and B for ks==1)
    // =======================================================================
    if (bid < NZ + NCVT) {
        const int c   = bid - NZ;
        const int bnb = c & 31;      // 128-row block of W/B
        const int ks  = c >> 5;      // 0..3 -> ktile range [ks*16, ks*16+16)

        for (int kt = ks * 16; kt < ks * 16 + 16; kt++) {
#pragma unroll
            for (int i = 0; i < 16; i++) {
                int idx = tid + i * 128;           // 0..2047 (128 rows x 16 f4)
                int row = bnb * 128 + (idx >> 4);
                int c4  = idx & 15;
                float4 v = W[(size_t)row * 1024 + kt * 16 + c4];
                uint2 o;
                o.x = pack2(v.x, v.y);
                o.y = pack2(v.z, v.w);
                ((uint2*)g_wh)[(size_t)row * 1024 + kt * 16 + c4] = o;
            }
            __threadfence();
            __syncthreads();
            if (tid == 0) set_flag(&g_flags[F_W + bnb * 64 + kt]);
        }

        if (ks == 1) {   // B rows [bnb*128, +128): 128 x 64 fp32
#pragma unroll
            for (int i = 0; i < 16; i++) {
                int idx = tid + i * 128;           // 0..2047
                int row = bnb * 128 + (idx >> 4);
                int c4  = idx & 15;
                float4 v = B[(size_t)row * 16 + c4];
                uint2 o;
                o.x = pack2(v.x, v.y);
                o.y = pack2(v.z, v.w);
                ((uint2*)g_bh)[(size_t)row * 16 + c4] = o;
            }
            __threadfence();
            __syncthreads();
            if (tid == 0) set_flag(&g_flags[F_B + bnb]);
        }
        __syncthreads();
        if (tid == 0) atomicAdd(&g_flags[F_DONE], 1);
        return;
    }

    // =======================================================================
    // main-GEMM role (R15 record structure + flag gating)
    // =======================================================================
    {
        constexpr int BM = 128, BN = 128, MT = 4, NT = 8;
        uint32_t* As = smem;                    // [2][BM][PITCH]
        uint32_t* Bs = smem + 2 * BM * PITCH;   // [2][BN][PITCH]

        const int wm = wid >> 1;
        const int wn = wid & 1;

        const int m  = bid - NPROD;
        const int bn = (m & 31) * BN;
        const int bm = (m >> 5) * BM;
        const int xb0 = bm / 64, xb1 = xb0 + 1;
        const int wb  = bn / 128;

        const bool fast = (*(volatile int*)&g_flags[F_DONE] == NPROD);

        float acc[MT][NT][4];
#pragma unroll
        for (int mt = 0; mt < MT; mt++)
#pragma unroll
            for (int nt = 0; nt < NT; nt++)
#pragma unroll
                for (int i = 0; i < 4; i++) acc[mt][nt][i] = 0.0f;

        const int KT = KT_MAIN + 1;             // + LoRA tile

        auto ensure = [&](int kb) {
            if (fast) return;
            if (tid == 0) {
                if (*(volatile int*)&g_flags[F_DONE] != NPROD) {
                    if (kb < KT_MAIN) {
                        spin_flag(&g_flags[F_X + xb0 * 64 + kb]);
                        spin_flag(&g_flags[F_X + xb1 * 64 + kb]);
                        spin_flag(&g_flags[F_W + wb * 64 + kb]);
                    } else {
                        spin_flag(&g_flags[F_ZS + xb0]);
                        spin_flag(&g_flags[F_ZS + xb1]);
                        spin_flag(&g_flags[F_B + wb]);
                    }
                }
                __threadfence();
            }
            __syncthreads();
        };

        auto issue_copy = [&](int kb, int stage) {
            uint32_t* as = As + stage * BM * PITCH;
            uint32_t* bs = Bs + stage * BN * PITCH;
            const bool main_k = (kb < KT_MAIN);
#pragma unroll
            for (int i = 0; i < BM / 16; i++) {
                int linear = tid + i * 128;
                int row = linear >> 3;
                int cv  = (linear & 7) << 2;
                const uint32_t* src = main_k
                    ? g_xh  + (size_t)(bm + row) * D_IN_P + (size_t)kb * 32 + cv
                    : g_zsh + (size_t)(bm + row) * R_P + cv;
                cp_async16(&as[row * PITCH + cv], src);
            }
#pragma unroll
            for (int i = 0; i < BN / 16; i++) {
                int linear = tid + i * 128;
                int row = linear >> 3;
                int cv  = (linear & 7) << 2;
                const uint32_t* src = main_k
                    ? g_wh + (size_t)(bn + row) * D_IN_P + (size_t)kb * 32 + cv
                    : g_bh + (size_t)(bn + row) * R_P + cv;
                cp_async16(&bs[row * PITCH + cv], src);
            }
            CPA_COMMIT();
        };

        ensure(0);
        issue_copy(0, 0);

        for (int kb = 0; kb < KT; kb++) {
            const int stage = kb & 1;
            if (kb + 1 < KT) {
                ensure(kb + 1);
                issue_copy(kb + 1, (kb + 1) & 1);
                CPA_WAIT(1);
            } else {
                CPA_WAIT(0);
            }
            __syncthreads();

            const uint32_t* as = As + stage * BM * PITCH + (wm * 64) * PITCH;
            const uint32_t* bs = Bs + stage * BN * PITCH + (wn * 64) * PITCH;

#pragma unroll
            for (int kk = 0; kk < 4; kk++) {
                uint32_t afrag[MT][4];
#pragma unroll
                for (int mt = 0; mt < MT; mt++) {
                    int r = mt * 16 + (lane >> 2);
                    int c = kk * 8 + (lane & 3);
                    afrag[mt][0] = as[r * PITCH + c];
                    afrag[mt][1] = as[(r + 8) * PITCH + c];
                    afrag[mt][2] = as[r * PITCH + c + 4];
                    afrag[mt][3] = as[(r + 8) * PITCH + c + 4];
                }
                uint32_t bfrag[NT][2];
#pragma unroll
                for (int nt = 0; nt < NT; nt++) {
                    int n = nt * 8 + (lane >> 2);
                    int c = kk * 8 + (lane & 3);
                    bfrag[nt][0] = bs[n * PITCH + c];
                    bfrag[nt][1] = bs[n * PITCH + c + 4];
                }
#pragma unroll
                for (int mt = 0; mt < MT; mt++)
#pragma unroll
                    for (int nt = 0; nt < NT; nt++)
                        mma_f16(acc[mt][nt], afrag[mt], bfrag[nt]);
            }
            __syncthreads();
        }

        // Epilogue: + bias, fp32 store
#pragma unroll
        for (int mt = 0; mt < MT; mt++) {
#pragma unroll
            for (int nt = 0; nt < NT; nt++) {
                int r0 = bm + wm * 64 + mt * 16 + (lane >> 2);
                int c0 = bn + wn * 64 + nt * 8 + (lane & 3) * 2;
                float b0 = __ldg(&bias[c0]), b1 = __ldg(&bias[c0 + 1]);
                float2 v0 = make_float2(acc[mt][nt][0] + b0, acc[mt][nt][1] + b1);
                float2 v1 = make_float2(acc[mt][nt][2] + b0, acc[mt][nt][3] + b1);
                *(float2*)&out[(size_t)r0 * N_FIX + c0]       = v0;
                *(float2*)&out[(size_t)(r0 + 8) * N_FIX + c0] = v1;
            }
        }
    }
}

// ---------------------------------------------------------------------------
extern "C" void kernel_launch(void* const* d_in, const int* in_sizes, int n_in,
                              void* d_out, int out_size)
{
    const float* x    = (const float*)d_in[0];
    const float* Amat = (const float*)d_in[1];
    const float* Bmat = (const float*)d_in[2];
    const float* Wmat = (const float*)d_in[3];
    const float* bias = (const float*)d_in[4];
    float* out = (float*)d_out;

    constexpr int SMEM = 2 * (128 + 128) * PITCH * 4;  // 73728 B
    cudaFuncSetAttribute(fused_kernel,
                         cudaFuncAttributeMaxDynamicSharedMemorySize, SMEM);

    // 1) reset flags (graph-replay determinism)
    reset_flags_kernel<<<32, 256>>>();

    // 2) fused: producers (z + cvt) overlapped with main GEMM via flags
    fused_kernel<<<NPROD + NMAIN, 128, SMEM>>>(
        (const float4*)x, (const float4*)Amat, (const float4*)Bmat,
        (const float4*)Wmat, bias, out);
}

// round 17
// speedup vs baseline: 1.0772x; 1.0772x over previous
#include <cuda_runtime.h>
#include <cuda_fp16.h>
#include <cstdint>

// ---------------------------------------------------------------------------
// FixedTopKLoRALinear: out = x@W^T + bias + softtopk(x@A^T)@B^T
// x[8192,4096], A[64,4096], B[4096,64], W[4096,4096], bias[4096]
//
// fp16 m16n8k16 mma.sync, fp32 accum. R15 record structure (842.8us) with ONE
// change: __launch_bounds__(128, 3) on gemm_main to force regs<=170 and
// 3 CTAs/SM (12 warps). R16 profiling showed tensor pipe only 51% busy at
// 2 CTAs/SM -> latency-bound, not HMMA-rate-bound; occupancy is the lever.
// Launches: (1) cvt A; (2) merged z-role (x cvt + z=x@A^T + topk) || W/B cvt;
// (3) main GEMM (LoRA fused as one extra K-tile + bias).
// ---------------------------------------------------------------------------

#define D_IN_C   4096
#define D_IN_P   2048          // fp16 pairs per x/W/A row
#define N_FIX    4096
#define R_C      64
#define R_P      32            // fp16 pairs per zs/B row
#define KSEL_C   16
#define TEMP_C   0.1f
#define MAX_M    8192
#define PITCH    36            // uint32 words per smem row

#define Z_BLOCKS   (MAX_M / 64)    // 128
#define CVT_BLOCKS 168

// Scratch (allocation-free: device globals)
__device__ uint32_t g_xh [MAX_M * D_IN_P];
__device__ uint32_t g_wh [N_FIX * D_IN_P];
__device__ uint32_t g_ah [R_C   * D_IN_P];
__device__ uint32_t g_bh [N_FIX * R_P];
__device__ uint32_t g_zsh[MAX_M * R_P];

// ---------------------------------------------------------------------------
__device__ __forceinline__ uint32_t pack2(float a, float b) {
    __half2 h = __floats2half2_rn(a, b);
    return *(uint32_t*)&h;
}

__device__ __forceinline__ void mma_f16(float* d, const uint32_t* a, const uint32_t* b) {
    asm volatile(
        "mma.sync.aligned.m16n8k16.row.col.f32.f16.f16.f32 "
        "{%0,%1,%2,%3},{%4,%5,%6,%7},{%8,%9},{%0,%1,%2,%3};"
        : "+f"(d[0]), "+f"(d[1]), "+f"(d[2]), "+f"(d[3])
        : "r"(a[0]), "r"(a[1]), "r"(a[2]), "r"(a[3]), "r"(b[0]), "r"(b[1]));
}

__device__ __forceinline__ void cp_async16(uint32_t* dst_smem, const uint32_t* src_gmem) {
    uint32_t s = (uint32_t)__cvta_generic_to_shared(dst_smem);
    asm volatile("cp.async.cg.shared.global [%0], [%1], 16;\n" :: "r"(s), "l"(src_gmem));
}
#define CPA_COMMIT() asm volatile("cp.async.commit_group;" ::: "memory")
#define CPA_WAIT(n)  asm volatile("cp.async.wait_group %0;" :: "n"(n) : "memory")

// ===========================================================================
// Kernel 1: convert A (fp32 -> fp16 pairs). 64x4096 = tiny.
// ===========================================================================
__global__ void cvt_a_kernel(const float4* __restrict__ A)
{
    const int n4 = R_C * D_IN_C / 4;   // 65536
    int i = blockIdx.x * blockDim.x + threadIdx.x;
    const int stride = gridDim.x * blockDim.x;
    uint2* dst = (uint2*)g_ah;
    for (; i < n4; i += stride) {
        float4 v = A[i];
        uint2 o;
        o.x = pack2(v.x, v.y);
        o.y = pack2(v.z, v.w);
        dst[i] = o;
    }
}

// ===========================================================================
// Kernel 2 (merged): blockIdx < Z_BLOCKS -> z-role; else -> W/B cvt role.
// z-role: 64-row block, 128 thr, 4 warps (2m x 2n), warp 32x32. Per 64-K
// tile: LDG x fp32 (prefetched) -> cvt -> STS + STG xh; cp.async A fp16 tile;
// mma. Epilogue: exact 16th-largest |z| soft mask -> zs fp16.
// cvt-role: grid-stride fp32->fp16 over W then B.
// ===========================================================================
__global__ void __launch_bounds__(128)
z_and_cvt_kernel(const float4* __restrict__ x,
                 const float4* __restrict__ W,
                 const float4* __restrict__ B)
{
    if (blockIdx.x >= Z_BLOCKS) {
        const int nW = N_FIX * D_IN_C / 4;   // 4194304
        const int nB = N_FIX * R_C / 4;      // 65536
        const int total = nW + nB;
        const int cvt_bid = blockIdx.x - Z_BLOCKS;
        int i = cvt_bid * blockDim.x + threadIdx.x;
        const int stride = CVT_BLOCKS * blockDim.x;
        for (; i < total; i += stride) {
            const float4* src; uint2* dst; int j;
            if (i < nW) { src = W; dst = (uint2*)g_wh; j = i; }
            else        { src = B; dst = (uint2*)g_bh; j = i - nW; }
            float4 v = src[j];
            uint2 o;
            o.x = pack2(v.x, v.y);
            o.y = pack2(v.z, v.w);
            dst[j] = o;
        }
        return;
    }

    // ---- z role ----
    extern __shared__ uint32_t smem[];
    uint32_t* As = smem;                  // [2][64][PITCH]
    uint32_t* Bs = smem + 2 * 64 * PITCH; // [2][64][PITCH]
    float*    zbuf = (float*)smem;        // [64][65], aliased after MMAs

    const int tid  = threadIdx.x;
    const int lane = tid & 31;
    const int wid  = tid >> 5;
    const int wm   = wid >> 1;
    const int wn   = wid & 1;
    const int bm   = blockIdx.x * 64;

    const int col4 = tid & 15;
    const int row0 = tid >> 4;

    float acc[2][4][4];
#pragma unroll
    for (int mt = 0; mt < 2; mt++)
#pragma unroll
        for (int nt = 0; nt < 4; nt++)
#pragma unroll
            for (int e = 0; e < 4; e++) acc[mt][nt][e] = 0.0f;

    auto ldg_x = [&](int kb, float4* r) {
#pragma unroll
        for (int i = 0; i < 8; i++)
            r[i] = x[(size_t)(bm + row0 + i * 8) * 1024 + kb * 16 + col4];
    };
    auto cpa_b = [&](int kb, int s) {
        uint32_t* bs = Bs + s * 64 * PITCH;
#pragma unroll
        for (int i = 0; i < 4; i++) {
            int linear = tid + i * 128;
            int row = linear >> 3;
            int cv  = (linear & 7) << 2;
            cp_async16(&bs[row * PITCH + cv],
                       g_ah + (size_t)row * D_IN_P + kb * 32 + cv);
        }
        CPA_COMMIT();
    };
    auto sts_stg = [&](int kb, int s, const float4* r) {
        uint32_t* as = As + s * 64 * PITCH;
        uint2* xo = (uint2*)g_xh;
#pragma unroll
        for (int i = 0; i < 8; i++) {
            uint2 v;
            v.x = pack2(r[i].x, r[i].y);
            v.y = pack2(r[i].z, r[i].w);
            int row = row0 + i * 8;
            *(uint2*)&as[row * PITCH + col4 * 2] = v;
            xo[(size_t)(bm + row) * 1024 + kb * 16 + col4] = v;
        }
    };
    auto mma_tile = [&](int s) {
        const uint32_t* as = As + s * 64 * PITCH + (wm * 32) * PITCH;
        const uint32_t* bs = Bs + s * 64 * PITCH + (wn * 32) * PITCH;
#pragma unroll
        for (int kk = 0; kk < 4; kk++) {
            uint32_t afrag[2][4];
#pragma unroll
            for (int mt = 0; mt < 2; mt++) {
                int r = mt * 16 + (lane >> 2);
                int c = kk * 8 + (lane & 3);
                afrag[mt][0] = as[r * PITCH + c];
                afrag[mt][1] = as[(r + 8) * PITCH + c];
                afrag[mt][2] = as[r * PITCH + c + 4];
                afrag[mt][3] = as[(r + 8) * PITCH + c + 4];
            }
            uint32_t bfrag[4][2];
#pragma unroll
            for (int nt = 0; nt < 4; nt++) {
                int n = nt * 8 + (lane >> 2);
                int c = kk * 8 + (lane & 3);
                bfrag[nt][0] = bs[n * PITCH + c];
                bfrag[nt][1] = bs[n * PITCH + c + 4];
            }
#pragma unroll
            for (int mt = 0; mt < 2; mt++)
#pragma unroll
                for (int nt = 0; nt < 4; nt++)
                    mma_f16(acc[mt][nt], afrag[mt], bfrag[nt]);
        }
    };

    const int KT = D_IN_C / 64;   // 64 (even)
    float4 rA[8], rB[8];
    ldg_x(0, rA);
    cpa_b(0, 0);

    for (int kb2 = 0; kb2 < KT; kb2 += 2) {
        if (kb2 + 1 < KT) { ldg_x(kb2 + 1, rB); cpa_b(kb2 + 1, 1); }
        sts_stg(kb2, 0, rA);
        if (kb2 + 1 < KT) { CPA_WAIT(1); } else { CPA_WAIT(0); }
        __syncthreads();
        mma_tile(0);
        __syncthreads();
        if (kb2 + 1 < KT) {
            if (kb2 + 2 < KT) { ldg_x(kb2 + 2, rA); cpa_b(kb2 + 2, 0); }
            sts_stg(kb2 + 1, 1, rB);
            if (kb2 + 2 < KT) { CPA_WAIT(1); } else { CPA_WAIT(0); }
            __syncthreads();
            mma_tile(1);
            __syncthreads();
        }
    }

    // ---- z -> smem (pitch 65 floats) ----
#pragma unroll
    for (int mt = 0; mt < 2; mt++)
#pragma unroll
        for (int nt = 0; nt < 4; nt++) {
            int r0 = wm * 32 + mt * 16 + (lane >> 2);
            int c0 = wn * 32 + nt * 8 + (lane & 3) * 2;
            zbuf[r0 * 65 + c0]           = acc[mt][nt][0];
            zbuf[r0 * 65 + c0 + 1]       = acc[mt][nt][1];
            zbuf[(r0 + 8) * 65 + c0]     = acc[mt][nt][2];
            zbuf[(r0 + 8) * 65 + c0 + 1] = acc[mt][nt][3];
        }
    __syncthreads();

    // ---- soft top-k per row; warp w handles rows w*16 .. w*16+15 ----
    const float inv_t = 1.0f / TEMP_C;
    for (int rr = 0; rr < 16; rr++) {
        const int row = wid * 16 + rr;
        float z0 = zbuf[row * 65 + lane];
        float z1 = zbuf[row * 65 + lane + 32];
        float v0 = fabsf(z0), v1 = fabsf(z1);
        bool a0 = true, a1 = true;
        float thr = 0.0f;
#pragma unroll 1
        for (int it = 0; it < KSEL_C; it++) {
            float m = fmaxf(a0 ? v0 : -1.0f, a1 ? v1 : -1.0f);
#pragma unroll
            for (int off = 16; off; off >>= 1)
                m = fmaxf(m, __shfl_xor_sync(0xffffffffu, m, off));
            thr = m;
            unsigned b = __ballot_sync(0xffffffffu, a0 && v0 == m);
            if (b) {
                if (lane == (__ffs(b) - 1)) a0 = false;
            } else {
                unsigned b2 = __ballot_sync(0xffffffffu, a1 && v1 == m);
                if (lane == (__ffs(b2) - 1)) a1 = false;
            }
        }
        float zs0 = z0 * (1.0f / (1.0f + expf(-(v0 - thr) * inv_t)));
        float zs1 = z1 * (1.0f / (1.0f + expf(-(v1 - thr) * inv_t)));
        zbuf[row * 65 + lane]      = zs0;
        zbuf[row * 65 + lane + 32] = zs1;
        __syncwarp();
        g_zsh[(size_t)(bm + row) * R_P + lane] =
            pack2(zbuf[row * 65 + 2 * lane], zbuf[row * 65 + 2 * lane + 1]);
        __syncwarp();
    }
}

// ===========================================================================
// Kernel 3: MAIN GEMM — R15 schedule, with __launch_bounds__(128, 3) to cap
// registers at 170 and lift occupancy to 3 CTAs/SM (12 warps).
// 128x128 CTA, 128 threads, 4 warps (2m x 2n), warp tile 64x64.
// K: 64 main tiles + 1 LoRA tile (zs @ B^T). 2-stage cp.async, pitch-36.
// ===========================================================================
__global__ void __launch_bounds__(128, 3)
gemm_main(const float* __restrict__ bias, float* __restrict__ out)
{
    constexpr int BM = 128, BN = 128, MT = 4, NT = 8;
    extern __shared__ uint32_t smem[];
    uint32_t* As = smem;                    // [2][BM][PITCH]
    uint32_t* Bs = smem + 2 * BM * PITCH;   // [2][BN][PITCH]

    const int tid  = threadIdx.x;
    const int lane = tid & 31;
    const int wid  = tid >> 5;
    const int wm   = wid >> 1;
    const int wn   = wid & 1;

    const int bm = blockIdx.y * BM;
    const int bn = blockIdx.x * BN;

    float acc[MT][NT][4];
#pragma unroll
    for (int mt = 0; mt < MT; mt++)
#pragma unroll
        for (int nt = 0; nt < NT; nt++)
#pragma unroll
            for (int i = 0; i < 4; i++) acc[mt][nt][i] = 0.0f;

    const int KT_main = D_IN_C / 64;        // 64
    const int KT = KT_main + 1;             // + LoRA tile

    auto issue_copy = [&](int kb, int stage) {
        uint32_t* as = As + stage * BM * PITCH;
        uint32_t* bs = Bs + stage * BN * PITCH;
        const bool main_k = (kb < KT_main);
#pragma unroll
        for (int i = 0; i < BM / 16; i++) {
            int linear = tid + i * 128;
            int row = linear >> 3;
            int cv  = (linear & 7) << 2;
            const uint32_t* src = main_k
                ? g_xh  + (size_t)(bm + row) * D_IN_P + (size_t)kb * 32 + cv
                : g_zsh + (size_t)(bm + row) * R_P + cv;
            cp_async16(&as[row * PITCH + cv], src);
        }
#pragma unroll
        for (int i = 0; i < BN / 16; i++) {
            int linear = tid + i * 128;
            int row = linear >> 3;
            int cv  = (linear & 7) << 2;
            const uint32_t* src = main_k
                ? g_wh + (size_t)(bn + row) * D_IN_P + (size_t)kb * 32 + cv
                : g_bh + (size_t)(bn + row) * R_P + cv;
            cp_async16(&bs[row * PITCH + cv], src);
        }
        CPA_COMMIT();
    };

    issue_copy(0, 0);

    for (int kb = 0; kb < KT; kb++) {
        const int stage = kb & 1;
        if (kb + 1 < KT) {
            issue_copy(kb + 1, (kb + 1) & 1);
            CPA_WAIT(1);
        } else {
            CPA_WAIT(0);
        }
        __syncthreads();

        const uint32_t* as = As + stage * BM * PITCH + (wm * 64) * PITCH;
        const uint32_t* bs = Bs + stage * BN * PITCH + (wn * 64) * PITCH;

#pragma unroll
        for (int kk = 0; kk < 4; kk++) {
            uint32_t afrag[MT][4];
#pragma unroll
            for (int mt = 0; mt < MT; mt++) {
                int r = mt * 16 + (lane >> 2);
                int c = kk * 8 + (lane & 3);
                afrag[mt][0] = as[r * PITCH + c];
                afrag[mt][1] = as[(r + 8) * PITCH + c];
                afrag[mt][2] = as[r * PITCH + c + 4];
                afrag[mt][3] = as[(r + 8) * PITCH + c + 4];
            }
            uint32_t bfrag[NT][2];
#pragma unroll
            for (int nt = 0; nt < NT; nt++) {
                int n = nt * 8 + (lane >> 2);
                int c = kk * 8 + (lane & 3);
                bfrag[nt][0] = bs[n * PITCH + c];
                bfrag[nt][1] = bs[n * PITCH + c + 4];
            }
#pragma unroll
            for (int mt = 0; mt < MT; mt++)
#pragma unroll
                for (int nt = 0; nt < NT; nt++)
                    mma_f16(acc[mt][nt], afrag[mt], bfrag[nt]);
        }
        __syncthreads();
    }

    // Epilogue: + bias, fp32 store
#pragma unroll
    for (int mt = 0; mt < MT; mt++) {
#pragma unroll
        for (int nt = 0; nt < NT; nt++) {
            int r0 = bm + wm * 64 + mt * 16 + (lane >> 2);
            int c0 = bn + wn * 64 + nt * 8 + (lane & 3) * 2;
            float b0 = __ldg(&bias[c0]), b1 = __ldg(&bias[c0 + 1]);
            float2 v0 = make_float2(acc[mt][nt][0] + b0, acc[mt][nt][1] + b1);
            float2 v1 = make_float2(acc[mt][nt][2] + b0, acc[mt][nt][3] + b1);
            *(float2*)&out[(size_t)r0 * N_FIX + c0]       = v0;
            *(float2*)&out[(size_t)(r0 + 8) * N_FIX + c0] = v1;
        }
    }
}

// ---------------------------------------------------------------------------
extern "C" void kernel_launch(void* const* d_in, const int* in_sizes, int n_in,
                              void* d_out, int out_size)
{
    const float* x    = (const float*)d_in[0];
    const float* Amat = (const float*)d_in[1];
    const float* Bmat = (const float*)d_in[2];
    const float* Wmat = (const float*)d_in[3];
    const float* bias = (const float*)d_in[4];
    float* out = (float*)d_out;

    const int M = in_sizes[0] / D_IN_C;          // 8192
    const int N = in_sizes[4];                   // 4096

    constexpr int SMEM_MAIN = 2 * (128 + 128) * PITCH * 4;  // 73728 B
    constexpr int SMEM_Z    = 2 * (64 + 64) * PITCH * 4;    // 36864 B
    cudaFuncSetAttribute(gemm_main,
                         cudaFuncAttributeMaxDynamicSharedMemorySize, SMEM_MAIN);
    cudaFuncSetAttribute(z_and_cvt_kernel,
                         cudaFuncAttributeMaxDynamicSharedMemorySize, SMEM_Z);

    // 1) A -> fp16 (tiny)
    cvt_a_kernel<<<64, 128>>>((const float4*)Amat);

    // 2) merged: z-role (x cvt + z + topk) || cvt-role (W/B -> fp16)
    z_and_cvt_kernel<<<Z_BLOCKS + CVT_BLOCKS, 128, SMEM_Z>>>(
        (const float4*)x, (const float4*)Wmat, (const float4*)Bmat);

    // 3) out = x@W^T + bias + zs@B^T (LoRA = extra K-tile)
    {
        dim3 grid(N / 128, M / 128);
        gemm_main<<<grid, 128, SMEM_MAIN>>>(bias, out);
    }
}